// round 1
// baseline (speedup 1.0000x reference)
#include <cuda_runtime.h>
#include <cstdint>

// Problem constants
#define NB 32
#define NS 512
#define NH 16
#define NDH 64
#define NDM 1024
#define NT 512
#define BH (NB*NH)          // 512

// Scratch (static __device__ arrays; allocation APIs are forbidden)
__device__ float g_Q [BH*NS*NDH];   // [bh][s][d]
__device__ float g_K [BH*NS*NDH];
__device__ float g_V [BH*NS*NDH];
__device__ float g_KE[BH*NDH*NT];   // [bh][d][t]
__device__ float g_VF[BH*NT*NDH];   // [bh][t][d]
__device__ float g_HO[BH*NS*NDH];   // [bh][s][d]
// Fallbacks in case out buffer holds only one of the two outputs
__device__ float g_ATTN_FB[(size_t)BH*NS*NT];
__device__ float g_MHA_FB [(size_t)NB*NS*NDM];

// ---------------------------------------------------------------------------
// Kernel 1: per-head Q/K/V projection.  out[bh][s][e] = in[b][s][:]·W[h][e][:] + b[h][e]
// grid (BH, S/64, 3), block 256
// ---------------------------------------------------------------------------
__global__ void k_qkv(const float* __restrict__ qin, const float* __restrict__ kin,
                      const float* __restrict__ vin,
                      const float* __restrict__ Wq, const float* __restrict__ bq,
                      const float* __restrict__ Wk, const float* __restrict__ bk,
                      const float* __restrict__ Wv, const float* __restrict__ bv)
{
    __shared__ float WT[64][65];   // WT[d][e]
    __shared__ float Xs[64][64];   // Xs[r][d]
    int bh = blockIdx.x;
    int b  = bh >> 4, h = bh & 15;
    int s0 = blockIdx.y << 6;
    const float *in, *W, *bias; float* out;
    if (blockIdx.z == 0)      { in = qin; W = Wq; bias = bq; out = g_Q; }
    else if (blockIdx.z == 1) { in = kin; W = Wk; bias = bk; out = g_K; }
    else                      { in = vin; W = Wv; bias = bv; out = g_V; }
    int tid = threadIdx.x;
    for (int i = tid; i < 4096; i += 256) {
        int r = i >> 6, c = i & 63;
        WT[c][r] = W[(h*64 + r)*64 + c];                 // W[h][e=r][d=c] -> WT[d][e]
        Xs[r][c] = in[((b*NS) + s0 + r)*64 + c];
    }
    __syncthreads();
    int e  = tid & 63;
    int ty = tid >> 6;                                   // 0..3
    float bval = bias[h*64 + e];
    float acc[16];
#pragma unroll
    for (int j = 0; j < 16; j++) acc[j] = bval;
#pragma unroll 4
    for (int d = 0; d < 64; d++) {
        float w = WT[d][e];
#pragma unroll
        for (int j = 0; j < 16; j++) acc[j] += Xs[ty + j*4][d] * w;
    }
#pragma unroll
    for (int j = 0; j < 16; j++)
        out[((size_t)bh*NS + s0 + ty + j*4)*64 + e] = acc[j];
}

// ---------------------------------------------------------------------------
// Kernel 2: KE[bh][d][t] = sum_s K[bh][s][d] * E_w[t][s] + E_b[t]
// grid (BH, T/128), block 256, dyn smem = Ks[64][64] + Es[128][65]
// ---------------------------------------------------------------------------
__global__ void k_ke(const float* __restrict__ Ew, const float* __restrict__ Eb)
{
    extern __shared__ float sm[];
    float* Ks = sm;              // [si][d]  (64x64)
    float* Es = sm + 4096;       // [tj][si] (128x65, padded)
    int bh = blockIdx.x;
    int t0 = blockIdx.y << 7;
    int tid = threadIdx.x;
    int txt = tid & 15;          // t = t0 + txt + 16*j
    int txd = tid >> 4;          // d = txd*4 + i
    float acc[4][8];
#pragma unroll
    for (int j = 0; j < 8; j++) {
        float eb = Eb[t0 + txt + 16*j];
#pragma unroll
        for (int i = 0; i < 4; i++) acc[i][j] = eb;
    }
    const float* Kp = g_K + (size_t)bh*NS*NDH;
    for (int s0 = 0; s0 < NS; s0 += 64) {
        __syncthreads();
        for (int i = tid; i < 4096; i += 256)
            Ks[i] = Kp[(s0 + (i >> 6))*64 + (i & 63)];
        for (int i = tid; i < 8192; i += 256) {
            int tj = i >> 6, si = i & 63;
            Es[tj*65 + si] = Ew[(t0 + tj)*NS + s0 + si];
        }
        __syncthreads();
#pragma unroll 4
        for (int si = 0; si < 64; si++) {
            float4 a4 = *reinterpret_cast<const float4*>(&Ks[si*64 + txd*4]);
            float a[4] = {a4.x, a4.y, a4.z, a4.w};
            float bb[8];
#pragma unroll
            for (int j = 0; j < 8; j++) bb[j] = Es[(txt + 16*j)*65 + si];
#pragma unroll
            for (int i = 0; i < 4; i++)
#pragma unroll
                for (int j = 0; j < 8; j++) acc[i][j] += a[i] * bb[j];
        }
    }
    float* KEp = g_KE + (size_t)bh*NDH*NT;
#pragma unroll
    for (int i = 0; i < 4; i++)
#pragma unroll
        for (int j = 0; j < 8; j++)
            KEp[(txd*4 + i)*NT + t0 + txt + 16*j] = acc[i][j];
}

// ---------------------------------------------------------------------------
// Kernel 3: VF[bh][t][d] = sum_s F_w[t][s] * V[bh][s][d] + F_b[t]
// grid (BH, T/128), block 256, dyn smem = Fs[128][64] + Vs[64][64]
// ---------------------------------------------------------------------------
__global__ void k_vf(const float* __restrict__ Fw, const float* __restrict__ Fb)
{
    extern __shared__ float sm[];
    float* Fs = sm;              // [tj][si] (128x64)
    float* Vs = sm + 8192;       // [si][d]  (64x64)
    int bh = blockIdx.x;
    int t0 = blockIdx.y << 7;
    int tid = threadIdx.x;
    int txd = tid & 15;          // d = txd*4 + i
    int txt = tid >> 4;          // t = t0 + txt*8 + j
    float acc[8][4];
#pragma unroll
    for (int j = 0; j < 8; j++) {
        float fb = Fb[t0 + txt*8 + j];
#pragma unroll
        for (int i = 0; i < 4; i++) acc[j][i] = fb;
    }
    const float* Vp = g_V + (size_t)bh*NS*NDH;
    for (int s0 = 0; s0 < NS; s0 += 64) {
        __syncthreads();
        for (int i = tid; i < 8192; i += 256) {
            int tj = i >> 6, si = i & 63;
            Fs[tj*64 + si] = Fw[(t0 + tj)*NS + s0 + si];
        }
        for (int i = tid; i < 4096; i += 256)
            Vs[i] = Vp[(s0 + (i >> 6))*64 + (i & 63)];
        __syncthreads();
#pragma unroll 4
        for (int si = 0; si < 64; si++) {
            float4 a4 = *reinterpret_cast<const float4*>(&Vs[si*64 + txd*4]);
            float a[4] = {a4.x, a4.y, a4.z, a4.w};
            float bb[8];
#pragma unroll
            for (int j = 0; j < 8; j++) bb[j] = Fs[(txt*8 + j)*64 + si];
#pragma unroll
            for (int j = 0; j < 8; j++)
#pragma unroll
                for (int i = 0; i < 4; i++) acc[j][i] += bb[j] * a[i];
        }
    }
    float* VFp = g_VF + (size_t)bh*NT*NDH;
#pragma unroll
    for (int j = 0; j < 8; j++) {
        float4 v = make_float4(acc[j][0], acc[j][1], acc[j][2], acc[j][3]);
        *reinterpret_cast<float4*>(&VFp[(t0 + txt*8 + j)*NDH + txd*4]) = v;
    }
}

// ---------------------------------------------------------------------------
// Kernel 4: scores = scale * Q·KE, softmax over t, write attn.
// grid (BH, S/64), block 512, dyn smem = KE[64][512] + Q[64][64] + red[2][16][8]
// ---------------------------------------------------------------------------
__global__ void __launch_bounds__(512, 1)
k_attn(float* __restrict__ attn_out)
{
    extern __shared__ float sm[];
    float* KEs  = sm;                 // [d][t]  64*512
    float* Qs   = sm + 64*512;        // [r][d]  64*64
    float* redm = Qs + 64*64;         // [warp][i] 16*8
    float* reds = redm + 128;         // [warp][i] 16*8
    int bh = blockIdx.x;
    int s0 = blockIdx.y << 6;
    int tid = threadIdx.x;            // 512

    const float* KEp = g_KE + (size_t)bh*NDH*NT;
    for (int i = tid; i < 64*512; i += 512) KEs[i] = KEp[i];
    const float* Qp = g_Q + ((size_t)bh*NS + s0)*NDH;
    for (int i = tid; i < 4096; i += 512) Qs[i] = Qp[i];
    __syncthreads();

    int txc = tid & 63;               // col base, c = txc + 64*j
    int tyr = tid >> 6;               // 0..7, row r = tyr*8 + i
    float acc[8][8];
#pragma unroll
    for (int i = 0; i < 8; i++)
#pragma unroll
        for (int j = 0; j < 8; j++) acc[i][j] = 0.f;

#pragma unroll 2
    for (int d = 0; d < 64; d++) {
        float qv[8], kv[8];
#pragma unroll
        for (int i = 0; i < 8; i++) qv[i] = Qs[(tyr*8 + i)*64 + d];
#pragma unroll
        for (int j = 0; j < 8; j++) kv[j] = KEs[d*512 + txc + 64*j];
#pragma unroll
        for (int i = 0; i < 8; i++)
#pragma unroll
            for (int j = 0; j < 8; j++) acc[i][j] += qv[i]*kv[j];
    }

    int warp = tid >> 5, lane = tid & 31;
    // row max
#pragma unroll
    for (int i = 0; i < 8; i++) {
        float m = -1e30f;
#pragma unroll
        for (int j = 0; j < 8; j++) { acc[i][j] *= 0.125f; m = fmaxf(m, acc[i][j]); }
#pragma unroll
        for (int o = 16; o; o >>= 1) m = fmaxf(m, __shfl_xor_sync(0xffffffffu, m, o));
        if (lane == 0) redm[warp*8 + i] = m;
    }
    __syncthreads();
    float rowm[8];
#pragma unroll
    for (int i = 0; i < 8; i++)
        rowm[i] = fmaxf(redm[(tyr*2)*8 + i], redm[(tyr*2 + 1)*8 + i]);
    // exp + row sum
#pragma unroll
    for (int i = 0; i < 8; i++) {
        float s = 0.f;
#pragma unroll
        for (int j = 0; j < 8; j++) { acc[i][j] = __expf(acc[i][j] - rowm[i]); s += acc[i][j]; }
#pragma unroll
        for (int o = 16; o; o >>= 1) s += __shfl_xor_sync(0xffffffffu, s, o);
        if (lane == 0) reds[warp*8 + i] = s;
    }
    __syncthreads();
#pragma unroll
    for (int i = 0; i < 8; i++) {
        float s = reds[(tyr*2)*8 + i] + reds[(tyr*2 + 1)*8 + i];
        float inv = 1.f / s;
        size_t base = ((size_t)bh*NS + s0 + tyr*8 + i)*NT;
#pragma unroll
        for (int j = 0; j < 8; j++)
            attn_out[base + txc + 64*j] = acc[i][j] * inv;
    }
}

// ---------------------------------------------------------------------------
// Kernel 5: head_out[bh][s][d] = sum_t attn[bh][s][t] * VF[bh][t][d]
// grid (BH, S/128), block 256, dyn smem = As[128][64] + Bs[64][64]
// ---------------------------------------------------------------------------
__global__ void k_ho(const float* __restrict__ attn)
{
    extern __shared__ float sm[];
    float* As = sm;              // [si][ti] 128x64
    float* Bs = sm + 8192;       // [ti][d]  64x64
    int bh = blockIdx.x;
    int s0 = blockIdx.y << 7;
    int tid = threadIdx.x;
    int txd = tid & 15;          // d = txd + 16*jd
    int tys = tid >> 4;          // s = s0 + tys*8 + is
    float acc[8][4];
#pragma unroll
    for (int a = 0; a < 8; a++)
#pragma unroll
        for (int c = 0; c < 4; c++) acc[a][c] = 0.f;

    const float* Ap = attn + (size_t)bh*NS*NT;
    const float* Bp = g_VF + (size_t)bh*NT*NDH;
    for (int t0 = 0; t0 < NT; t0 += 64) {
        __syncthreads();
        for (int i = tid; i < 8192; i += 256) {
            int si = i >> 6, ti = i & 63;
            As[si*64 + ti] = Ap[(s0 + si)*NT + t0 + ti];
        }
        for (int i = tid; i < 4096; i += 256)
            Bs[i] = Bp[(t0 + (i >> 6))*64 + (i & 63)];
        __syncthreads();
#pragma unroll 4
        for (int ti = 0; ti < 64; ti++) {
            float a[8], bb[4];
#pragma unroll
            for (int is = 0; is < 8; is++) a[is] = As[(tys*8 + is)*64 + ti];
#pragma unroll
            for (int jd = 0; jd < 4; jd++) bb[jd] = Bs[ti*64 + txd + 16*jd];
#pragma unroll
            for (int is = 0; is < 8; is++)
#pragma unroll
                for (int jd = 0; jd < 4; jd++) acc[is][jd] += a[is]*bb[jd];
        }
    }
    float* Op = g_HO + (size_t)bh*NS*NDH;
#pragma unroll
    for (int is = 0; is < 8; is++)
#pragma unroll
        for (int jd = 0; jd < 4; jd++)
            Op[(s0 + tys*8 + is)*NDH + txd + 16*jd] = acc[is][jd];
}

// ---------------------------------------------------------------------------
// Kernel 6: out[b][s][n] = sum_k mha[b][s][k]*out_w[n][k] + out_b[n]
//           mha[b][s][h*64+d] = g_HO[(b*16+h)][s][d]
// grid (M/64, N/128), block 256, dyn smem = As[64][64] + Ws[128][65]
// ---------------------------------------------------------------------------
__global__ void k_out(const float* __restrict__ Ow, const float* __restrict__ Ob,
                      float* __restrict__ out)
{
    extern __shared__ float sm[];
    float* As = sm;              // [mi][ki] 64x64
    float* Ws = sm + 4096;       // [nj][ki] 128x65 padded
    int m0 = blockIdx.x << 6;    // m = b*512 + s
    int n0 = blockIdx.y << 7;
    int b  = m0 >> 9;
    int sb = m0 & 511;
    int tid = threadIdx.x;
    int txn = tid & 15;          // n = n0 + txn + 16*j
    int txm = tid >> 4;          // m = m0 + txm*4 + i
    float acc[4][8];
#pragma unroll
    for (int j = 0; j < 8; j++) {
        float ob = Ob[n0 + txn + 16*j];
#pragma unroll
        for (int i = 0; i < 4; i++) acc[i][j] = ob;
    }
    for (int k0 = 0; k0 < NDM; k0 += 64) {
        int h = k0 >> 6;
        __syncthreads();
        const float* HOp = g_HO + ((size_t)(b*NH + h)*NS)*NDH;
        for (int i = tid; i < 4096; i += 256) {
            int mi = i >> 6, ki = i & 63;
            As[mi*64 + ki] = HOp[(sb + mi)*NDH + ki];
        }
        for (int i = tid; i < 8192; i += 256) {
            int nj = i >> 6, ki = i & 63;
            Ws[nj*65 + ki] = Ow[(n0 + nj)*NDM + k0 + ki];
        }
        __syncthreads();
#pragma unroll 4
        for (int ki = 0; ki < 64; ki++) {
            float a[4], bb[8];
#pragma unroll
            for (int i = 0; i < 4; i++) a[i] = As[(txm*4 + i)*64 + ki];
#pragma unroll
            for (int j = 0; j < 8; j++) bb[j] = Ws[(txn + 16*j)*65 + ki];
#pragma unroll
            for (int i = 0; i < 4; i++)
#pragma unroll
                for (int j = 0; j < 8; j++) acc[i][j] += a[i]*bb[j];
        }
    }
#pragma unroll
    for (int i = 0; i < 4; i++)
#pragma unroll
        for (int j = 0; j < 8; j++)
            out[(size_t)(m0 + txm*4 + i)*NDM + n0 + txn + 16*j] = acc[i][j];
}

// ---------------------------------------------------------------------------
extern "C" void kernel_launch(void* const* d_in, const int* in_sizes, int n_in,
                              void* d_out, int out_size)
{
    const float* query = (const float*)d_in[0];
    const float* key   = (const float*)d_in[1];
    const float* value = (const float*)d_in[2];
    const float* Wq    = (const float*)d_in[3];
    const float* bq    = (const float*)d_in[4];
    const float* Wk    = (const float*)d_in[5];
    const float* bk    = (const float*)d_in[6];
    const float* Wv    = (const float*)d_in[7];
    const float* bv    = (const float*)d_in[8];
    const float* E_w   = (const float*)d_in[9];
    const float* E_b   = (const float*)d_in[10];
    const float* F_w   = (const float*)d_in[11];
    const float* F_b   = (const float*)d_in[12];
    const float* out_w = (const float*)d_in[13];
    const float* out_b = (const float*)d_in[14];

    const long long mha_elems  = (long long)NB*NS*NDM;      // 16,777,216
    const long long attn_elems = (long long)BH*NS*NT;       // 134,217,728

    float* outp = (float*)d_out;
    float* mha_ptr;
    float* attn_ptr;
    if ((long long)out_size >= mha_elems + attn_elems) {
        mha_ptr  = outp;
        attn_ptr = outp + mha_elems;
    } else if ((long long)out_size == attn_elems) {
        // only attn expected
        attn_ptr = outp;
        cudaGetSymbolAddress((void**)&mha_ptr, g_MHA_FB);
    } else {
        // only mha expected
        mha_ptr = outp;
        cudaGetSymbolAddress((void**)&attn_ptr, g_ATTN_FB);
    }

    cudaFuncSetAttribute(k_ke,   cudaFuncAttributeMaxDynamicSharedMemorySize, 49664);
    cudaFuncSetAttribute(k_vf,   cudaFuncAttributeMaxDynamicSharedMemorySize, 49152);
    cudaFuncSetAttribute(k_attn, cudaFuncAttributeMaxDynamicSharedMemorySize, 148480);
    cudaFuncSetAttribute(k_ho,   cudaFuncAttributeMaxDynamicSharedMemorySize, 49152);
    cudaFuncSetAttribute(k_out,  cudaFuncAttributeMaxDynamicSharedMemorySize, 49664);

    k_qkv<<<dim3(BH, NS/64, 3), 256>>>(query, key, value, Wq, bq, Wk, bk, Wv, bv);
    k_ke <<<dim3(BH, NT/128), 256, 49664>>>(E_w, E_b);
    k_vf <<<dim3(BH, NT/128), 256, 49152>>>(F_w, F_b);
    k_attn<<<dim3(BH, NS/64), 512, 148480>>>(attn_ptr);
    k_ho <<<dim3(BH, NS/128), 256, 49152>>>(attn_ptr);
    k_out<<<dim3((NB*NS)/64, NDM/128), 256, 49664>>>(out_w, out_b, mha_ptr);
}

// round 4
// speedup vs baseline: 1.1506x; 1.1506x over previous
#include <cuda_runtime.h>
#include <cuda_bf16.h>
#include <cstdint>

// Problem constants
#define NB 32
#define NS 512
#define NH 16
#define NDH 64
#define NDM 1024
#define NT 512
#define BH (NB*NH)          // 512

// ---------------- global scratch (static; allocation APIs forbidden) -------
__device__ float g_Q [BH*NS*NDH];   // [bh][s][d]
__device__ float g_K [BH*NS*NDH];
__device__ float g_V [BH*NS*NDH];
__device__ float g_KE[BH*NDH*NT];   // [bh][d][t]  (consumed by k_attn)
__device__ float g_VF[BH*NT*NDH];   // [bh][t][d]  (consumed by k_ho)
// bf16 split operands for mma.sync GEMMs
__device__ __nv_bfloat16 g_Kth[(size_t)BH*NDH*NS];   // K^T [bh][d][s]
__device__ __nv_bfloat16 g_Ktl[(size_t)BH*NDH*NS];
__device__ __nv_bfloat16 g_Vth[(size_t)BH*NDH*NS];   // V^T [bh][d][s]
__device__ __nv_bfloat16 g_Vtl[(size_t)BH*NDH*NS];
__device__ __nv_bfloat16 g_Ewh[NT*NS], g_Ewl[NT*NS];
__device__ __nv_bfloat16 g_Fwh[NT*NS], g_Fwl[NT*NS];
__device__ __nv_bfloat16 g_Owh[NDM*NDM], g_Owl[NDM*NDM];
__device__ __nv_bfloat16 g_HOh[(size_t)BH*NS*NDH];   // head_out [bh][s][d]
__device__ __nv_bfloat16 g_HOl[(size_t)BH*NS*NDH];
// Fallbacks in case out buffer holds only one of the two outputs
__device__ float g_ATTN_FB[(size_t)BH*NS*NT];
__device__ float g_MHA_FB [(size_t)NB*NS*NDM];

// ---------------- mma.sync helper (sm_80+ baseline feature) ----------------
__device__ __forceinline__ void mma16816(float c[4],
                                         uint32_t a0, uint32_t a1, uint32_t a2, uint32_t a3,
                                         uint32_t b0, uint32_t b1)
{
    asm volatile(
        "mma.sync.aligned.m16n8k16.row.col.f32.bf16.bf16.f32 "
        "{%0,%1,%2,%3}, {%4,%5,%6,%7}, {%8,%9}, {%0,%1,%2,%3};"
        : "+f"(c[0]), "+f"(c[1]), "+f"(c[2]), "+f"(c[3])
        : "r"(a0), "r"(a1), "r"(a2), "r"(a3), "r"(b0), "r"(b1));
}

// ---------------------------------------------------------------------------
// Kernel 1: per-head Q/K/V projection (fp32, validated round 1)
// ---------------------------------------------------------------------------
__global__ void k_qkv(const float* __restrict__ qin, const float* __restrict__ kin,
                      const float* __restrict__ vin,
                      const float* __restrict__ Wq, const float* __restrict__ bq,
                      const float* __restrict__ Wk, const float* __restrict__ bk,
                      const float* __restrict__ Wv, const float* __restrict__ bv)
{
    __shared__ float WT[64][65];
    __shared__ float Xs[64][64];
    int bh = blockIdx.x;
    int b  = bh >> 4, h = bh & 15;
    int s0 = blockIdx.y << 6;
    const float *in, *W, *bias; float* out;
    if (blockIdx.z == 0)      { in = qin; W = Wq; bias = bq; out = g_Q; }
    else if (blockIdx.z == 1) { in = kin; W = Wk; bias = bk; out = g_K; }
    else                      { in = vin; W = Wv; bias = bv; out = g_V; }
    int tid = threadIdx.x;
    for (int i = tid; i < 4096; i += 256) {
        int r = i >> 6, c = i & 63;
        WT[c][r] = W[(h*64 + r)*64 + c];
        Xs[r][c] = in[((b*NS) + s0 + r)*64 + c];
    }
    __syncthreads();
    int e  = tid & 63;
    int ty = tid >> 6;
    float bval = bias[h*64 + e];
    float acc[16];
#pragma unroll
    for (int j = 0; j < 16; j++) acc[j] = bval;
#pragma unroll 4
    for (int d = 0; d < 64; d++) {
        float w = WT[d][e];
#pragma unroll
        for (int j = 0; j < 16; j++) acc[j] += Xs[ty + j*4][d] * w;
    }
#pragma unroll
    for (int j = 0; j < 16; j++)
        out[((size_t)bh*NS + s0 + ty + j*4)*64 + e] = acc[j];
}

// ---------------------------------------------------------------------------
// Kernel: elementwise bf16 split (hi + lo)
// ---------------------------------------------------------------------------
__global__ void k_split(const float* __restrict__ s, __nv_bfloat16* __restrict__ h,
                        __nv_bfloat16* __restrict__ l, int n)
{
    int i = blockIdx.x * 256 + threadIdx.x;
    if (i < n) {
        float v = s[i];
        __nv_bfloat16 hb = __float2bfloat16(v);
        h[i] = hb;
        l[i] = __float2bfloat16(v - __bfloat162float(hb));
    }
}

// ---------------------------------------------------------------------------
// Kernel: transpose K/V to [d][s] + bf16 split
// ---------------------------------------------------------------------------
__global__ void k_prep_kv()
{
    __shared__ float ts[64][65];
    int bh = blockIdx.x, s0 = blockIdx.y << 6;
    const float* src = (blockIdx.z == 0 ? g_K : g_V) + (size_t)bh*NS*NDH;
    __nv_bfloat16* dh = (blockIdx.z == 0 ? g_Kth : g_Vth) + (size_t)bh*NDH*NS;
    __nv_bfloat16* dl = (blockIdx.z == 0 ? g_Ktl : g_Vtl) + (size_t)bh*NDH*NS;
    int tid = threadIdx.x;
    for (int i = tid; i < 4096; i += 256) {
        int r = i >> 6, c = i & 63;
        ts[r][c] = src[(s0 + r)*64 + c];
    }
    __syncthreads();
    for (int i = tid; i < 4096; i += 256) {
        int d = i >> 6, r = i & 63;
        float v = ts[r][d];
        __nv_bfloat16 hb = __float2bfloat16(v);
        dh[(size_t)d*NS + s0 + r] = hb;
        dl[(size_t)d*NS + s0 + r] = __float2bfloat16(v - __bfloat162float(hb));
    }
}

// ===========================================================================
// mma.sync GEMM template body (shared structure)
// Block 256 = 8 warps, warp (wm = wid&3, wn = wid>>2) owns 32(m)x32(n).
// smem: Ah[128][33] Al[128][33] Bh[64][33] Bl[64][33] as u32 (bf16 pairs),
//       rows padded +1 u32 -> conflict-free fragment loads.
// Per 16-k step: 2 A-frags (hi+lo) + 4 B-frags (hi+lo), 24 MMAs (hh,hl,lh).
// ===========================================================================
#define MMA_CHUNK_COMPUTE()                                                      \
    _Pragma("unroll")                                                            \
    for (int ks = 0; ks < 4; ks++) {                                             \
        int kw = ks*8;                                                           \
        uint32_t ah[2][4], al[2][4];                                             \
        _Pragma("unroll")                                                        \
        for (int mi = 0; mi < 2; mi++) {                                         \
            int base = (m0w + mi*16 + g)*33 + kw + t4;                           \
            ah[mi][0] = Ah32[base];     ah[mi][1] = Ah32[base + 264];            \
            ah[mi][2] = Ah32[base + 4]; ah[mi][3] = Ah32[base + 268];            \
            al[mi][0] = Al32[base];     al[mi][1] = Al32[base + 264];            \
            al[mi][2] = Al32[base + 4]; al[mi][3] = Al32[base + 268];            \
        }                                                                        \
        _Pragma("unroll")                                                        \
        for (int nj = 0; nj < 4; nj++) {                                         \
            int bb = (n0w + nj*8 + g)*33 + kw + t4;                              \
            uint32_t b0h = Bh32[bb], b1h = Bh32[bb + 4];                         \
            uint32_t b0l = Bl32[bb], b1l = Bl32[bb + 4];                         \
            _Pragma("unroll")                                                    \
            for (int mi = 0; mi < 2; mi++) {                                     \
                mma16816(acc[mi][nj], ah[mi][0],ah[mi][1],ah[mi][2],ah[mi][3], b0h,b1h); \
                mma16816(acc[mi][nj], ah[mi][0],ah[mi][1],ah[mi][2],ah[mi][3], b0l,b1l); \
                mma16816(acc[mi][nj], al[mi][0],al[mi][1],al[mi][2],al[mi][3], b0h,b1h); \
            }                                                                    \
        }                                                                        \
    }

// ---------------------------------------------------------------------------
// k_ke_mma: D[t(128)][d(64)] = sum_s Ew[t][s]*Kt[d][s]; +Eb[t]; store KE[d][t]
// grid (BH, 4), block 256, dyn smem 50688
// ---------------------------------------------------------------------------
__global__ void __launch_bounds__(256, 2) k_ke_mma(const float* __restrict__ Eb)
{
    extern __shared__ uint32_t sm32[];
    uint32_t* Ah32 = sm32;
    uint32_t* Al32 = Ah32 + 128*33;
    uint32_t* Bh32 = Al32 + 128*33;
    uint32_t* Bl32 = Bh32 + 64*33;
    int tid = threadIdx.x, wid = tid >> 5, lane = tid & 31;
    int g = lane >> 2, t4 = lane & 3;
    int m0w = (wid & 3)*32, n0w = (wid >> 2)*32;
    int bh = blockIdx.x, t0 = blockIdx.y << 7;

    float acc[2][4][4];
#pragma unroll
    for (int mi = 0; mi < 2; mi++)
#pragma unroll
        for (int nj = 0; nj < 4; nj++)
#pragma unroll
            for (int q = 0; q < 4; q++) acc[mi][nj][q] = 0.f;

    const uint32_t* gAh = (const uint32_t*)g_Ewh + (size_t)t0*256;
    const uint32_t* gAl = (const uint32_t*)g_Ewl + (size_t)t0*256;
    const uint32_t* gBh = (const uint32_t*)g_Kth + (size_t)bh*16384;
    const uint32_t* gBl = (const uint32_t*)g_Ktl + (size_t)bh*16384;

    for (int ch = 0; ch < 8; ch++) {
        int sw = ch*32;
        __syncthreads();
        for (int i = tid; i < 4096; i += 256) {
            int r = i >> 5, c = i & 31;
            Ah32[r*33 + c] = gAh[(size_t)r*256 + sw + c];
            Al32[r*33 + c] = gAl[(size_t)r*256 + sw + c];
        }
        for (int i = tid; i < 2048; i += 256) {
            int r = i >> 5, c = i & 31;
            Bh32[r*33 + c] = gBh[(size_t)r*256 + sw + c];
            Bl32[r*33 + c] = gBl[(size_t)r*256 + sw + c];
        }
        __syncthreads();
        MMA_CHUNK_COMPUTE();
    }

    // epilogue: stage transposed [d][t], add Eb[t], store g_KE
    __syncthreads();
    float* Sg = (float*)sm32;          // [64][129] = 33024 B
#pragma unroll
    for (int mi = 0; mi < 2; mi++) {
        int m = m0w + mi*16 + g;
        float e0 = Eb[t0 + m];
        float e1 = Eb[t0 + m + 8];
#pragma unroll
        for (int nj = 0; nj < 4; nj++) {
            int n = n0w + nj*8 + t4*2;
            Sg[n*129 + m]         = acc[mi][nj][0] + e0;
            Sg[(n+1)*129 + m]     = acc[mi][nj][1] + e0;
            Sg[n*129 + m + 8]     = acc[mi][nj][2] + e1;
            Sg[(n+1)*129 + m + 8] = acc[mi][nj][3] + e1;
        }
    }
    __syncthreads();
    float* dst = g_KE + (size_t)bh*NDH*NT + t0;
    for (int i = tid; i < 8192; i += 256) {
        int d = i >> 7, m = i & 127;
        dst[(size_t)d*NT + m] = Sg[d*129 + m];
    }
}

// ---------------------------------------------------------------------------
// k_vf_mma: D[t(128)][d(64)] = sum_s Fw[t][s]*Vt[d][s]; +Fb[t]; store VF[t][d]
// ---------------------------------------------------------------------------
__global__ void __launch_bounds__(256, 2) k_vf_mma(const float* __restrict__ Fb)
{
    extern __shared__ uint32_t sm32[];
    uint32_t* Ah32 = sm32;
    uint32_t* Al32 = Ah32 + 128*33;
    uint32_t* Bh32 = Al32 + 128*33;
    uint32_t* Bl32 = Bh32 + 64*33;
    int tid = threadIdx.x, wid = tid >> 5, lane = tid & 31;
    int g = lane >> 2, t4 = lane & 3;
    int m0w = (wid & 3)*32, n0w = (wid >> 2)*32;
    int bh = blockIdx.x, t0 = blockIdx.y << 7;

    float acc[2][4][4];
#pragma unroll
    for (int mi = 0; mi < 2; mi++)
#pragma unroll
        for (int nj = 0; nj < 4; nj++)
#pragma unroll
            for (int q = 0; q < 4; q++) acc[mi][nj][q] = 0.f;

    const uint32_t* gAh = (const uint32_t*)g_Fwh + (size_t)t0*256;
    const uint32_t* gAl = (const uint32_t*)g_Fwl + (size_t)t0*256;
    const uint32_t* gBh = (const uint32_t*)g_Vth + (size_t)bh*16384;
    const uint32_t* gBl = (const uint32_t*)g_Vtl + (size_t)bh*16384;

    for (int ch = 0; ch < 8; ch++) {
        int sw = ch*32;
        __syncthreads();
        for (int i = tid; i < 4096; i += 256) {
            int r = i >> 5, c = i & 31;
            Ah32[r*33 + c] = gAh[(size_t)r*256 + sw + c];
            Al32[r*33 + c] = gAl[(size_t)r*256 + sw + c];
        }
        for (int i = tid; i < 2048; i += 256) {
            int r = i >> 5, c = i & 31;
            Bh32[r*33 + c] = gBh[(size_t)r*256 + sw + c];
            Bl32[r*33 + c] = gBl[(size_t)r*256 + sw + c];
        }
        __syncthreads();
        MMA_CHUNK_COMPUTE();
    }

    // epilogue: stage [t][d], add Fb[t], store g_VF
    __syncthreads();
    float* Sg = (float*)sm32;          // [128][65] = 33280 B
#pragma unroll
    for (int mi = 0; mi < 2; mi++) {
        int m = m0w + mi*16 + g;
        float f0 = Fb[t0 + m];
        float f1 = Fb[t0 + m + 8];
#pragma unroll
        for (int nj = 0; nj < 4; nj++) {
            int n = n0w + nj*8 + t4*2;
            Sg[m*65 + n]         = acc[mi][nj][0] + f0;
            Sg[m*65 + n + 1]     = acc[mi][nj][1] + f0;
            Sg[(m+8)*65 + n]     = acc[mi][nj][2] + f1;
            Sg[(m+8)*65 + n + 1] = acc[mi][nj][3] + f1;
        }
    }
    __syncthreads();
    float* dst = g_VF + (size_t)bh*NT*NDH + (size_t)t0*NDH;
    for (int i = tid; i < 8192; i += 256) {
        int r = i >> 6, c = i & 63;
        dst[(size_t)r*NDH + c] = Sg[r*65 + c];
    }
}

// ---------------------------------------------------------------------------
// k_out_mma: out[m(128)][n(64)] = sum_k HO[m][k]*Ow[n][k] + Ob[n]
// grid (128 m-tiles, 16 n-tiles), block 256, K=1024 in 16 head-chunks
// ---------------------------------------------------------------------------
__global__ void __launch_bounds__(256, 2) k_out_mma(const float* __restrict__ Ob,
                                                    float* __restrict__ out)
{
    extern __shared__ uint32_t sm32[];
    uint32_t* Ah32 = sm32;
    uint32_t* Al32 = Ah32 + 128*33;
    uint32_t* Bh32 = Al32 + 128*33;
    uint32_t* Bl32 = Bh32 + 64*33;
    int tid = threadIdx.x, wid = tid >> 5, lane = tid & 31;
    int g = lane >> 2, t4 = lane & 3;
    int m0w = (wid & 3)*32, n0w = (wid >> 2)*32;
    int m0 = blockIdx.x << 7;
    int b  = blockIdx.x >> 2;
    int sbase = (blockIdx.x & 3) << 7;
    int n0 = blockIdx.y << 6;

    float acc[2][4][4];
#pragma unroll
    for (int mi = 0; mi < 2; mi++)
#pragma unroll
        for (int nj = 0; nj < 4; nj++)
#pragma unroll
            for (int q = 0; q < 4; q++) acc[mi][nj][q] = 0.f;

    for (int kc = 0; kc < 16; kc++) {
        const uint32_t* gAh = (const uint32_t*)g_HOh + ((size_t)(b*NH + kc)*NS + sbase)*32;
        const uint32_t* gAl = (const uint32_t*)g_HOl + ((size_t)(b*NH + kc)*NS + sbase)*32;
        const uint32_t* gBh = (const uint32_t*)g_Owh + (size_t)n0*512 + kc*32;
        const uint32_t* gBl = (const uint32_t*)g_Owl + (size_t)n0*512 + kc*32;
        __syncthreads();
        for (int i = tid; i < 4096; i += 256) {
            int r = i >> 5, c = i & 31;
            Ah32[r*33 + c] = gAh[(size_t)r*32 + c];
            Al32[r*33 + c] = gAl[(size_t)r*32 + c];
        }
        for (int i = tid; i < 2048; i += 256) {
            int r = i >> 5, c = i & 31;
            Bh32[r*33 + c] = gBh[(size_t)r*512 + c];
            Bl32[r*33 + c] = gBl[(size_t)r*512 + c];
        }
        __syncthreads();
        MMA_CHUNK_COMPUTE();
    }

    // epilogue: stage [m][n], add Ob[n], store out
    __syncthreads();
    float* Sg = (float*)sm32;          // [128][65]
#pragma unroll
    for (int mi = 0; mi < 2; mi++) {
        int m = m0w + mi*16 + g;
#pragma unroll
        for (int nj = 0; nj < 4; nj++) {
            int n = n0w + nj*8 + t4*2;
            float o0 = Ob[n0 + n];
            float o1 = Ob[n0 + n + 1];
            Sg[m*65 + n]         = acc[mi][nj][0] + o0;
            Sg[m*65 + n + 1]     = acc[mi][nj][1] + o1;
            Sg[(m+8)*65 + n]     = acc[mi][nj][2] + o0;
            Sg[(m+8)*65 + n + 1] = acc[mi][nj][3] + o1;
        }
    }
    __syncthreads();
    for (int i = tid; i < 8192; i += 256) {
        int r = i >> 6, c = i & 63;
        out[(size_t)(m0 + r)*NDM + n0 + c] = Sg[r*65 + c];
    }
}

// ---------------------------------------------------------------------------
// Kernel 4: scores = scale * Q·KE, softmax over t, write attn. (fp32)
// ---------------------------------------------------------------------------
__global__ void __launch_bounds__(512, 1)
k_attn(float* __restrict__ attn_out)
{
    extern __shared__ float sm[];
    float* KEs  = sm;
    float* Qs   = sm + 64*512;
    float* redm = Qs + 64*64;
    float* reds = redm + 128;
    int bh = blockIdx.x;
    int s0 = blockIdx.y << 6;
    int tid = threadIdx.x;

    const float* KEp = g_KE + (size_t)bh*NDH*NT;
    for (int i = tid; i < 64*512; i += 512) KEs[i] = KEp[i];
    const float* Qp = g_Q + ((size_t)bh*NS + s0)*NDH;
    for (int i = tid; i < 4096; i += 512) Qs[i] = Qp[i];
    __syncthreads();

    int txc = tid & 63;
    int tyr = tid >> 6;
    float acc[8][8];
#pragma unroll
    for (int i = 0; i < 8; i++)
#pragma unroll
        for (int j = 0; j < 8; j++) acc[i][j] = 0.f;

#pragma unroll 2
    for (int d = 0; d < 64; d++) {
        float qv[8], kv[8];
#pragma unroll
        for (int i = 0; i < 8; i++) qv[i] = Qs[(tyr*8 + i)*64 + d];
#pragma unroll
        for (int j = 0; j < 8; j++) kv[j] = KEs[d*512 + txc + 64*j];
#pragma unroll
        for (int i = 0; i < 8; i++)
#pragma unroll
            for (int j = 0; j < 8; j++) acc[i][j] += qv[i]*kv[j];
    }

    int warp = tid >> 5, lane = tid & 31;
#pragma unroll
    for (int i = 0; i < 8; i++) {
        float m = -1e30f;
#pragma unroll
        for (int j = 0; j < 8; j++) { acc[i][j] *= 0.125f; m = fmaxf(m, acc[i][j]); }
#pragma unroll
        for (int o = 16; o; o >>= 1) m = fmaxf(m, __shfl_xor_sync(0xffffffffu, m, o));
        if (lane == 0) redm[warp*8 + i] = m;
    }
    __syncthreads();
    float rowm[8];
#pragma unroll
    for (int i = 0; i < 8; i++)
        rowm[i] = fmaxf(redm[(tyr*2)*8 + i], redm[(tyr*2 + 1)*8 + i]);
#pragma unroll
    for (int i = 0; i < 8; i++) {
        float s = 0.f;
#pragma unroll
        for (int j = 0; j < 8; j++) { acc[i][j] = __expf(acc[i][j] - rowm[i]); s += acc[i][j]; }
#pragma unroll
        for (int o = 16; o; o >>= 1) s += __shfl_xor_sync(0xffffffffu, s, o);
        if (lane == 0) reds[warp*8 + i] = s;
    }
    __syncthreads();
#pragma unroll
    for (int i = 0; i < 8; i++) {
        float s = reds[(tyr*2)*8 + i] + reds[(tyr*2 + 1)*8 + i];
        float inv = 1.f / s;
        size_t base = ((size_t)bh*NS + s0 + tyr*8 + i)*NT;
#pragma unroll
        for (int j = 0; j < 8; j++)
            attn_out[base + txc + 64*j] = acc[i][j] * inv;
    }
}

// ---------------------------------------------------------------------------
// Kernel 5: head_out = attn·VF (fp32) — epilogue writes bf16 split HO
// ---------------------------------------------------------------------------
__global__ void k_ho(const float* __restrict__ attn)
{
    extern __shared__ float sm[];
    float* As = sm;
    float* Bs = sm + 8192;
    int bh = blockIdx.x;
    int s0 = blockIdx.y << 7;
    int tid = threadIdx.x;
    int txd = tid & 15;
    int tys = tid >> 4;
    float acc[8][4];
#pragma unroll
    for (int a = 0; a < 8; a++)
#pragma unroll
        for (int c = 0; c < 4; c++) acc[a][c] = 0.f;

    const float* Ap = attn + (size_t)bh*NS*NT;
    const float* Bp = g_VF + (size_t)bh*NT*NDH;
    for (int t0 = 0; t0 < NT; t0 += 64) {
        __syncthreads();
        for (int i = tid; i < 8192; i += 256) {
            int si = i >> 6, ti = i & 63;
            As[si*64 + ti] = Ap[(s0 + si)*NT + t0 + ti];
        }
        for (int i = tid; i < 4096; i += 256)
            Bs[i] = Bp[(t0 + (i >> 6))*64 + (i & 63)];
        __syncthreads();
#pragma unroll 4
        for (int ti = 0; ti < 64; ti++) {
            float a[8], bb[4];
#pragma unroll
            for (int is = 0; is < 8; is++) a[is] = As[(tys*8 + is)*64 + ti];
#pragma unroll
            for (int jd = 0; jd < 4; jd++) bb[jd] = Bs[ti*64 + txd + 16*jd];
#pragma unroll
            for (int is = 0; is < 8; is++)
#pragma unroll
                for (int jd = 0; jd < 4; jd++) acc[is][jd] += a[is]*bb[jd];
        }
    }
    size_t base = (size_t)bh*NS*NDH;
#pragma unroll
    for (int is = 0; is < 8; is++)
#pragma unroll
        for (int jd = 0; jd < 4; jd++) {
            size_t idx = base + (size_t)(s0 + tys*8 + is)*NDH + txd + 16*jd;
            float v = acc[is][jd];
            __nv_bfloat16 hb = __float2bfloat16(v);
            g_HOh[idx] = hb;
            g_HOl[idx] = __float2bfloat16(v - __bfloat162float(hb));
        }
}

// ---------------------------------------------------------------------------
extern "C" void kernel_launch(void* const* d_in, const int* in_sizes, int n_in,
                              void* d_out, int out_size)
{
    const float* query = (const float*)d_in[0];
    const float* key   = (const float*)d_in[1];
    const float* value = (const float*)d_in[2];
    const float* Wq    = (const float*)d_in[3];
    const float* bq    = (const float*)d_in[4];
    const float* Wk    = (const float*)d_in[5];
    const float* bk    = (const float*)d_in[6];
    const float* Wv    = (const float*)d_in[7];
    const float* bv    = (const float*)d_in[8];
    const float* E_w   = (const float*)d_in[9];
    const float* E_b   = (const float*)d_in[10];
    const float* F_w   = (const float*)d_in[11];
    const float* F_b   = (const float*)d_in[12];
    const float* out_w = (const float*)d_in[13];
    const float* out_b = (const float*)d_in[14];

    const long long mha_elems  = (long long)NB*NS*NDM;
    const long long attn_elems = (long long)BH*NS*NT;

    float* outp = (float*)d_out;
    float* mha_ptr;
    float* attn_ptr;
    if ((long long)out_size >= mha_elems + attn_elems) {
        mha_ptr  = outp;
        attn_ptr = outp + mha_elems;
    } else if ((long long)out_size == attn_elems) {
        attn_ptr = outp;
        cudaGetSymbolAddress((void**)&mha_ptr, g_MHA_FB);
    } else {
        mha_ptr = outp;
        cudaGetSymbolAddress((void**)&attn_ptr, g_ATTN_FB);
    }

    __nv_bfloat16 *ewh, *ewl, *fwh, *fwl, *owh, *owl;
    cudaGetSymbolAddress((void**)&ewh, g_Ewh); cudaGetSymbolAddress((void**)&ewl, g_Ewl);
    cudaGetSymbolAddress((void**)&fwh, g_Fwh); cudaGetSymbolAddress((void**)&fwl, g_Fwl);
    cudaGetSymbolAddress((void**)&owh, g_Owh); cudaGetSymbolAddress((void**)&owl, g_Owl);

    cudaFuncSetAttribute(k_ke_mma,  cudaFuncAttributeMaxDynamicSharedMemorySize, 50688);
    cudaFuncSetAttribute(k_vf_mma,  cudaFuncAttributeMaxDynamicSharedMemorySize, 50688);
    cudaFuncSetAttribute(k_out_mma, cudaFuncAttributeMaxDynamicSharedMemorySize, 50688);
    cudaFuncSetAttribute(k_attn,    cudaFuncAttributeMaxDynamicSharedMemorySize, 148480);
    cudaFuncSetAttribute(k_ho,      cudaFuncAttributeMaxDynamicSharedMemorySize, 49152);

    k_qkv<<<dim3(BH, NS/64, 3), 256>>>(query, key, value, Wq, bq, Wk, bk, Wv, bv);
    k_split<<<(NT*NS + 255)/256, 256>>>(E_w, ewh, ewl, NT*NS);
    k_split<<<(NT*NS + 255)/256, 256>>>(F_w, fwh, fwl, NT*NS);
    k_split<<<(NDM*NDM + 255)/256, 256>>>(out_w, owh, owl, NDM*NDM);
    k_prep_kv<<<dim3(BH, NS/64, 2), 256>>>();
    k_ke_mma<<<dim3(BH, 4), 256, 50688>>>(E_b);
    k_vf_mma<<<dim3(BH, 4), 256, 50688>>>(F_b);
    k_attn<<<dim3(BH, NS/64), 512, 148480>>>(attn_ptr);
    k_ho  <<<dim3(BH, NS/128), 256, 49152>>>(attn_ptr);
    k_out_mma<<<dim3((NB*NS)/128, NDM/64), 256, 50688>>>(out_b, mha_ptr);
}